// round 13
// baseline (speedup 1.0000x reference)
#include <cuda_runtime.h>

#define NB      32
#define NIN     1034
#define NOUT    512
#define STRIDE  1088
#define KNS     1000.0f
#define MINW    (-0.3678794411714423f)
#define EF      2.718281828459045f
#define NBUCK   2048
#define GROUP   8
#define ITILES  33          // ceil(1034/32)
#define OTILES  16          // 512/32

// packed per-batch sorted data: (t, e^t, t*e^t, idx-as-int-bits)
__device__ float4 g_pack[NB * STRIDE];
// transposed weights: Wt[i][o], 1034 x 512
__device__ float  g_wt[NIN * NOUT];

__device__ __forceinline__ float get_t(const float* __restrict__ x,
                                       const float* __restrict__ pulse,
                                       int b, int i) {
    return (i < 1024) ? x[b * 1024 + i] : pulse[i - 1024];
}

__device__ __forceinline__ int bucket_of(float t) {
    int bid = (int)(t * (float)NBUCK);
    return bid < 0 ? 0 : (bid >= NBUCK ? NBUCK - 1 : bid);
}

// ---------------------------------------------------------------------------
// Kernel 1 (fused): blocks 0..31 -> per-batch bucket sort + pack;
//                   blocks 32..559 -> 32x32 transpose tiles of W.
// ---------------------------------------------------------------------------
__global__ void prep_kernel(const float* __restrict__ x,
                            const float* __restrict__ pulse,
                            const float* __restrict__ W) {
    __shared__ int cnt [NBUCK];
    __shared__ int base[NBUCK];
    __shared__ unsigned long long keys[NIN];
    __shared__ float wsum[32];
    __shared__ float tile[32][33];

    const int bid = blockIdx.x;
    const int tid = threadIdx.x;

    if (bid >= NB) {
        const int tb = bid - NB;
        const int i0 = (tb % ITILES) * 32;
        const int o0 = (tb / ITILES) * 32;
        const int tx = tid & 31, ty = tid >> 5;
        const int i = i0 + tx;
        if (i < NIN) tile[ty][tx] = W[(o0 + ty) * NIN + i];
        __syncthreads();
        const int i2 = i0 + ty;
        if (i2 < NIN) g_wt[i2 * NOUT + o0 + tx] = tile[tx][ty];
        return;
    }

    const int b = bid;
    const int lane = tid & 31, wid = tid >> 5;

    cnt[tid] = 0; cnt[tid + 1024] = 0;
    __syncthreads();

    for (int i = tid; i < NIN; i += 1024) {
        const float t = get_t(x, pulse, b, i);
        atomicAdd(&cnt[bucket_of(t)], 1);
    }
    __syncthreads();

    {
        const int v0 = cnt[2 * tid], v1 = cnt[2 * tid + 1];
        float s = (float)(v0 + v1);
        #pragma unroll
        for (int off = 1; off < 32; off <<= 1) {
            const float u = __shfl_up_sync(0xffffffffu, s, off);
            if (lane >= off) s += u;
        }
        if (lane == 31) wsum[wid] = s;
        __syncthreads();
        if (wid == 0) {
            float ws = wsum[lane];
            #pragma unroll
            for (int off = 1; off < 32; off <<= 1) {
                const float u = __shfl_up_sync(0xffffffffu, ws, off);
                if (lane >= off) ws += u;
            }
            wsum[lane] = ws;
        }
        __syncthreads();
        const int incl = (int)s + (wid ? (int)wsum[wid - 1] : 0);
        const int excl = incl - v0 - v1;
        base[2 * tid]     = excl;
        base[2 * tid + 1] = excl + v0;
        __syncthreads();
        cnt[2 * tid]     = excl;
        cnt[2 * tid + 1] = excl + v0;
    }
    __syncthreads();

    for (int i = tid; i < NIN; i += 1024) {
        const float t = get_t(x, pulse, b, i);
        const int pos = atomicAdd(&cnt[bucket_of(t)], 1);
        keys[pos] = ((unsigned long long)__float_as_uint(t) << 32) | (unsigned)i;
    }
    __syncthreads();

    for (int bk = tid; bk < NBUCK; bk += 1024) {
        const int s0 = base[bk];
        const int s1 = (bk + 1 < NBUCK) ? base[bk + 1] : NIN;
        for (int i = s0 + 1; i < s1; ++i) {
            const unsigned long long v = keys[i];
            int j = i - 1;
            while (j >= s0 && keys[j] > v) { keys[j + 1] = keys[j]; --j; }
            keys[j + 1] = v;
        }
    }
    __syncthreads();

    for (int i = tid; i < STRIDE; i += 1024) {
        if (i < NIN) {
            const unsigned long long v = keys[i];
            const float t = __uint_as_float((unsigned)(v >> 32));
            const int idx = (int)(unsigned)v;
            const float z = expf(t);
            g_pack[b * STRIDE + i] = make_float4(t, z, z * t, __int_as_float(idx));
        } else {
            g_pack[b * STRIDE + i] = make_float4(KNS, 0.0f, 0.0f, 0.0f);
        }
    }
}

// ---------------------------------------------------------------------------
// Kernel 2: one THREAD per (batch, output); one b per 32-thread block.
// pk staged in shared memory; weight lines prefetched one group ahead;
// branchless first-valid latch; one Lambert solve at the end.
// ---------------------------------------------------------------------------
__global__ void __launch_bounds__(32)
solve_kernel(float* __restrict__ out) {
    __shared__ float4 spk[STRIDE];

    const int tid = threadIdx.x;
    const int gt  = blockIdx.x * 32 + tid;
    const int b   = gt >> 9;
    const int o   = gt & 511;

    // stage this batch row's packed data (coalesced, 17.4 KB)
    {
        const float4* __restrict__ pk = g_pack + b * STRIDE;
        #pragma unroll 4
        for (int i = tid; i < STRIDE; i += 32) spk[i] = pk[i];
    }
    __syncthreads();

    const float* __restrict__ wt = g_wt;

    float A = 0.0f, Bv = 0.0f;
    float fA = 1.0f, fB = 0.0f;
    bool  found = false;

    // prime: weights for group 0
    float w[GROUP];
    #pragma unroll
    for (int j = 0; j < GROUP; ++j)
        w[j] = wt[__float_as_int(spk[j].w) * NOUT + o];

    for (int k0 = 0; k0 < NIN; k0 += GROUP) {
        // prefetch next group's weight lines (coalesced; idx via cheap LDS)
        float wn[GROUP];
        #pragma unroll
        for (int j = 0; j < GROUP; ++j)
            wn[j] = wt[__float_as_int(spk[k0 + GROUP + j].w) * NOUT + o];

        // current group's pk entries + lookahead head (LDS, pipelined)
        float4 p[GROUP];
        #pragma unroll
        for (int j = 0; j < GROUP; ++j) p[j] = spk[k0 + j];
        const float4 q = spk[k0 + GROUP];

        // accumulate + branchless first-valid latch
        #pragma unroll
        for (int j = 0; j < GROUP; ++j) {
            A  = fmaf(w[j], p[j].y, A);
            Bv = fmaf(w[j], p[j].z, Bv);
            const float tn = (j < GROUP - 1) ? p[j + 1].x : q.x;
            const float zn = (j < GROUP - 1) ? p[j + 1].y : q.y;
            const float lnA = __logf(A);
            const bool valid =
                   (A > 1e-10f)
                && (fmaf(A, lnA - 1.0f, -Bv) >= 0.0f)        // reach: arg >= -1/e
                && (fmaf(A, p[j].x, -Bv) <= p[j].y)          // t* >= t_k
                && ((tn >= lnA) || (fmaf(A, tn, -Bv) >= zn)) // t* <= t_{k+1}
                && (p[j].x < KNS);
            const bool take = valid && !found;
            fA = take ? A  : fA;
            fB = take ? Bv : fB;
            found |= valid;
        }

        if (__all_sync(0xffffffffu, found)) break;

        #pragma unroll
        for (int j = 0; j < GROUP; ++j) w[j] = wn[j];
    }

    // one Lambert solve per thread
    float tc = KNS;
    if (found) {
        const float boa = fB / fA;
        float xw = -1.0f / fA * expf(fminf(boa, 80.0f));
        xw = fmaxf(fminf(xw, 0.0f), MINW);
        float wv;
        if (xw < -0.25f) {
            const float pbr = sqrtf(fmaxf(2.0f * (1.0f + EF * xw), 0.0f));
            wv = -1.0f + pbr * (1.0f + pbr * (-0.33333333f + pbr * 0.15277778f));
        } else {
            wv = xw * (1.0f - xw * (1.0f - 1.5f * xw));
        }
        #pragma unroll
        for (int it = 0; it < 3; ++it) {
            const float ew = expf(wv);
            const float f  = wv * ew - xw;
            const float denom = ew * (wv + 1.0f)
                      - (wv + 2.0f) * f / (2.0f * (wv + 1.0f) + 1e-12f);
            wv = wv - f / (denom + 1e-12f);
        }
        tc = boa - wv;
    }
    out[b * NOUT + o] = tc;
}

// ---------------------------------------------------------------------------
extern "C" void kernel_launch(void* const* d_in, const int* in_sizes, int n_in,
                              void* d_out, int out_size) {
    const float* x      = (const float*)d_in[0];   // [32, 1024]
    const float* weight = (const float*)d_in[1];   // [512, 1034]
    const float* pulse  = (const float*)d_in[2];   // [10]
    float* out = (float*)d_out;                    // [32, 512]

    prep_kernel<<<NB + ITILES * OTILES, 1024>>>(x, pulse, weight);

    // one thread per (b,o); one b per 32-thread block
    solve_kernel<<<(NB * NOUT) / 32, 32>>>(out);
}

// round 14
// speedup vs baseline: 1.4324x; 1.4324x over previous
#include <cuda_runtime.h>

#define NB      32
#define NIN     1034
#define NOUT    512
#define STRIDE  1088
#define KNS     1000.0f
#define MINW    (-0.3678794411714423f)
#define EF      2.718281828459045f
#define NBUCK   2048
#define GROUP   8
#define ITILES  33          // ceil(1034/32)
#define OTILES  16          // 512/32

// packed per-batch sorted data: (t, e^t, t*e^t, idx-as-int-bits)
__device__ float4 g_pack[NB * STRIDE];
// transposed weights: Wt[i][o], 1034 x 512
__device__ float  g_wt[NIN * NOUT];

__device__ __forceinline__ float get_t(const float* __restrict__ x,
                                       const float* __restrict__ pulse,
                                       int b, int i) {
    return (i < 1024) ? x[b * 1024 + i] : pulse[i - 1024];
}

__device__ __forceinline__ int bucket_of(float t) {
    int bid = (int)(t * (float)NBUCK);
    return bid < 0 ? 0 : (bid >= NBUCK ? NBUCK - 1 : bid);
}

// ---------------------------------------------------------------------------
// Kernel 1 (fused): blocks 0..31 -> per-batch bucket sort + pack;
//                   blocks 32..559 -> 32x32 transpose tiles of W.
// ---------------------------------------------------------------------------
__global__ void prep_kernel(const float* __restrict__ x,
                            const float* __restrict__ pulse,
                            const float* __restrict__ W) {
    __shared__ int cnt [NBUCK];
    __shared__ int base[NBUCK];
    __shared__ unsigned long long keys[NIN];
    __shared__ float wsum[32];
    __shared__ float tile[32][33];

    const int bid = blockIdx.x;
    const int tid = threadIdx.x;

    if (bid >= NB) {
        const int tb = bid - NB;
        const int i0 = (tb % ITILES) * 32;
        const int o0 = (tb / ITILES) * 32;
        const int tx = tid & 31, ty = tid >> 5;
        const int i = i0 + tx;
        if (i < NIN) tile[ty][tx] = W[(o0 + ty) * NIN + i];
        __syncthreads();
        const int i2 = i0 + ty;
        if (i2 < NIN) g_wt[i2 * NOUT + o0 + tx] = tile[tx][ty];
        return;
    }

    const int b = bid;
    const int lane = tid & 31, wid = tid >> 5;

    cnt[tid] = 0; cnt[tid + 1024] = 0;
    __syncthreads();

    for (int i = tid; i < NIN; i += 1024) {
        const float t = get_t(x, pulse, b, i);
        atomicAdd(&cnt[bucket_of(t)], 1);
    }
    __syncthreads();

    {
        const int v0 = cnt[2 * tid], v1 = cnt[2 * tid + 1];
        float s = (float)(v0 + v1);
        #pragma unroll
        for (int off = 1; off < 32; off <<= 1) {
            const float u = __shfl_up_sync(0xffffffffu, s, off);
            if (lane >= off) s += u;
        }
        if (lane == 31) wsum[wid] = s;
        __syncthreads();
        if (wid == 0) {
            float ws = wsum[lane];
            #pragma unroll
            for (int off = 1; off < 32; off <<= 1) {
                const float u = __shfl_up_sync(0xffffffffu, ws, off);
                if (lane >= off) ws += u;
            }
            wsum[lane] = ws;
        }
        __syncthreads();
        const int incl = (int)s + (wid ? (int)wsum[wid - 1] : 0);
        const int excl = incl - v0 - v1;
        base[2 * tid]     = excl;
        base[2 * tid + 1] = excl + v0;
        __syncthreads();
        cnt[2 * tid]     = excl;
        cnt[2 * tid + 1] = excl + v0;
    }
    __syncthreads();

    for (int i = tid; i < NIN; i += 1024) {
        const float t = get_t(x, pulse, b, i);
        const int pos = atomicAdd(&cnt[bucket_of(t)], 1);
        keys[pos] = ((unsigned long long)__float_as_uint(t) << 32) | (unsigned)i;
    }
    __syncthreads();

    for (int bk = tid; bk < NBUCK; bk += 1024) {
        const int s0 = base[bk];
        const int s1 = (bk + 1 < NBUCK) ? base[bk + 1] : NIN;
        for (int i = s0 + 1; i < s1; ++i) {
            const unsigned long long v = keys[i];
            int j = i - 1;
            while (j >= s0 && keys[j] > v) { keys[j + 1] = keys[j]; --j; }
            keys[j + 1] = v;
        }
    }
    __syncthreads();

    for (int i = tid; i < STRIDE; i += 1024) {
        if (i < NIN) {
            const unsigned long long v = keys[i];
            const float t = __uint_as_float((unsigned)(v >> 32));
            const int idx = (int)(unsigned)v;
            const float z = expf(t);
            g_pack[b * STRIDE + i] = make_float4(t, z, z * t, __int_as_float(idx));
        } else {
            g_pack[b * STRIDE + i] = make_float4(KNS, 0.0f, 0.0f, 0.0f);
        }
    }
}

// ---------------------------------------------------------------------------
// Kernel 2: one THREAD per (batch, output); one b per 32-thread block.
// pk staged in shared memory; weight lines prefetched one group ahead;
// branchless first-valid latch; one Lambert solve at the end.
// ---------------------------------------------------------------------------
__global__ void __launch_bounds__(32)
solve_kernel(float* __restrict__ out) {
    __shared__ float4 spk[STRIDE];

    const int tid = threadIdx.x;
    const int gt  = blockIdx.x * 32 + tid;
    const int b   = gt >> 9;
    const int o   = gt & 511;

    // stage this batch row's packed data (coalesced, 17.4 KB)
    {
        const float4* __restrict__ pk = g_pack + b * STRIDE;
        #pragma unroll 4
        for (int i = tid; i < STRIDE; i += 32) spk[i] = pk[i];
    }
    __syncthreads();

    const float* __restrict__ wt = g_wt;

    float A = 0.0f, Bv = 0.0f;
    float fA = 1.0f, fB = 0.0f;
    bool  found = false;

    // prime: weights for group 0
    float w[GROUP];
    #pragma unroll
    for (int j = 0; j < GROUP; ++j)
        w[j] = wt[__float_as_int(spk[j].w) * NOUT + o];

    for (int k0 = 0; k0 < NIN; k0 += GROUP) {
        // prefetch next group's weight lines (coalesced; idx via cheap LDS)
        float wn[GROUP];
        #pragma unroll
        for (int j = 0; j < GROUP; ++j)
            wn[j] = wt[__float_as_int(spk[k0 + GROUP + j].w) * NOUT + o];

        // current group's pk entries + lookahead head (LDS, pipelined)
        float4 p[GROUP];
        #pragma unroll
        for (int j = 0; j < GROUP; ++j) p[j] = spk[k0 + j];
        const float4 q = spk[k0 + GROUP];

        // accumulate + branchless first-valid latch
        #pragma unroll
        for (int j = 0; j < GROUP; ++j) {
            A  = fmaf(w[j], p[j].y, A);
            Bv = fmaf(w[j], p[j].z, Bv);
            const float tn = (j < GROUP - 1) ? p[j + 1].x : q.x;
            const float zn = (j < GROUP - 1) ? p[j + 1].y : q.y;
            const float lnA = __logf(A);
            const bool valid =
                   (A > 1e-10f)
                && (fmaf(A, lnA - 1.0f, -Bv) >= 0.0f)        // reach: arg >= -1/e
                && (fmaf(A, p[j].x, -Bv) <= p[j].y)          // t* >= t_k
                && ((tn >= lnA) || (fmaf(A, tn, -Bv) >= zn)) // t* <= t_{k+1}
                && (p[j].x < KNS);
            const bool take = valid && !found;
            fA = take ? A  : fA;
            fB = take ? Bv : fB;
            found |= valid;
        }

        if (__all_sync(0xffffffffu, found)) break;

        #pragma unroll
        for (int j = 0; j < GROUP; ++j) w[j] = wn[j];
    }

    // one Lambert solve per thread
    float tc = KNS;
    if (found) {
        const float boa = fB / fA;
        float xw = -1.0f / fA * expf(fminf(boa, 80.0f));
        xw = fmaxf(fminf(xw, 0.0f), MINW);
        float wv;
        if (xw < -0.25f) {
            const float pbr = sqrtf(fmaxf(2.0f * (1.0f + EF * xw), 0.0f));
            wv = -1.0f + pbr * (1.0f + pbr * (-0.33333333f + pbr * 0.15277778f));
        } else {
            wv = xw * (1.0f - xw * (1.0f - 1.5f * xw));
        }
        #pragma unroll
        for (int it = 0; it < 3; ++it) {
            const float ew = expf(wv);
            const float f  = wv * ew - xw;
            const float denom = ew * (wv + 1.0f)
                      - (wv + 2.0f) * f / (2.0f * (wv + 1.0f) + 1e-12f);
            wv = wv - f / (denom + 1e-12f);
        }
        tc = boa - wv;
    }
    out[b * NOUT + o] = tc;
}

// ---------------------------------------------------------------------------
extern "C" void kernel_launch(void* const* d_in, const int* in_sizes, int n_in,
                              void* d_out, int out_size) {
    const float* x      = (const float*)d_in[0];   // [32, 1024]
    const float* weight = (const float*)d_in[1];   // [512, 1034]
    const float* pulse  = (const float*)d_in[2];   // [10]
    float* out = (float*)d_out;                    // [32, 512]

    prep_kernel<<<NB + ITILES * OTILES, 1024>>>(x, pulse, weight);

    // one thread per (b,o); one b per 32-thread block
    solve_kernel<<<(NB * NOUT) / 32, 32>>>(out);
}

// round 15
// speedup vs baseline: 1.7928x; 1.2516x over previous
#include <cuda_runtime.h>

#define NB      32
#define NIN     1034
#define NOUT    512
#define STRIDE  1088
#define KNS     1000.0f
#define MINW    (-0.3678794411714423f)
#define EF      2.718281828459045f
#define NBUCK   2048
#define GROUP   16
#define ITILES  33          // ceil(1034/32)
#define OTILES  16          // 512/32

// packed per-batch sorted data: (t, e^t, t*e^t, idx-as-int-bits)
__device__ float4 g_pack[NB * STRIDE];
// transposed weights: Wt[i][o], 1034 x 512
__device__ float  g_wt[NIN * NOUT];

__device__ __forceinline__ float get_t(const float* __restrict__ x,
                                       const float* __restrict__ pulse,
                                       int b, int i) {
    return (i < 1024) ? x[b * 1024 + i] : pulse[i - 1024];
}

__device__ __forceinline__ int bucket_of(float t) {
    int bid = (int)(t * (float)NBUCK);
    return bid < 0 ? 0 : (bid >= NBUCK ? NBUCK - 1 : bid);
}

// ---------------------------------------------------------------------------
// Kernel 1 (fused): blocks 0..31 -> per-batch bucket sort + pack;
//                   blocks 32..559 -> 32x32 transpose tiles of W.
// ---------------------------------------------------------------------------
__global__ void prep_kernel(const float* __restrict__ x,
                            const float* __restrict__ pulse,
                            const float* __restrict__ W) {
    __shared__ int cnt [NBUCK];
    __shared__ int base[NBUCK];
    __shared__ unsigned long long keys[NIN];
    __shared__ float wsum[32];
    __shared__ float tile[32][33];

    const int bid = blockIdx.x;
    const int tid = threadIdx.x;

    if (bid >= NB) {
        const int tb = bid - NB;
        const int i0 = (tb % ITILES) * 32;
        const int o0 = (tb / ITILES) * 32;
        const int tx = tid & 31, ty = tid >> 5;
        const int i = i0 + tx;
        if (i < NIN) tile[ty][tx] = W[(o0 + ty) * NIN + i];
        __syncthreads();
        const int i2 = i0 + ty;
        if (i2 < NIN) g_wt[i2 * NOUT + o0 + tx] = tile[tx][ty];
        return;
    }

    const int b = bid;
    const int lane = tid & 31, wid = tid >> 5;

    cnt[tid] = 0; cnt[tid + 1024] = 0;
    __syncthreads();

    for (int i = tid; i < NIN; i += 1024) {
        const float t = get_t(x, pulse, b, i);
        atomicAdd(&cnt[bucket_of(t)], 1);
    }
    __syncthreads();

    {
        const int v0 = cnt[2 * tid], v1 = cnt[2 * tid + 1];
        float s = (float)(v0 + v1);
        #pragma unroll
        for (int off = 1; off < 32; off <<= 1) {
            const float u = __shfl_up_sync(0xffffffffu, s, off);
            if (lane >= off) s += u;
        }
        if (lane == 31) wsum[wid] = s;
        __syncthreads();
        if (wid == 0) {
            float ws = wsum[lane];
            #pragma unroll
            for (int off = 1; off < 32; off <<= 1) {
                const float u = __shfl_up_sync(0xffffffffu, ws, off);
                if (lane >= off) ws += u;
            }
            wsum[lane] = ws;
        }
        __syncthreads();
        const int incl = (int)s + (wid ? (int)wsum[wid - 1] : 0);
        const int excl = incl - v0 - v1;
        base[2 * tid]     = excl;
        base[2 * tid + 1] = excl + v0;
        __syncthreads();
        cnt[2 * tid]     = excl;
        cnt[2 * tid + 1] = excl + v0;
    }
    __syncthreads();

    for (int i = tid; i < NIN; i += 1024) {
        const float t = get_t(x, pulse, b, i);
        const int pos = atomicAdd(&cnt[bucket_of(t)], 1);
        keys[pos] = ((unsigned long long)__float_as_uint(t) << 32) | (unsigned)i;
    }
    __syncthreads();

    for (int bk = tid; bk < NBUCK; bk += 1024) {
        const int s0 = base[bk];
        const int s1 = (bk + 1 < NBUCK) ? base[bk + 1] : NIN;
        for (int i = s0 + 1; i < s1; ++i) {
            const unsigned long long v = keys[i];
            int j = i - 1;
            while (j >= s0 && keys[j] > v) { keys[j + 1] = keys[j]; --j; }
            keys[j + 1] = v;
        }
    }
    __syncthreads();

    for (int i = tid; i < STRIDE; i += 1024) {
        if (i < NIN) {
            const unsigned long long v = keys[i];
            const float t = __uint_as_float((unsigned)(v >> 32));
            const int idx = (int)(unsigned)v;
            const float z = expf(t);
            g_pack[b * STRIDE + i] = make_float4(t, z, z * t, __int_as_float(idx));
        } else {
            g_pack[b * STRIDE + i] = make_float4(KNS, 0.0f, 0.0f, 0.0f);
        }
    }
}

// ---------------------------------------------------------------------------
// Kernel 2: one THREAD per (batch, output); 64-thr blocks (8 per batch row).
// pk in smem. Per group of 16: accumulate-only FMA chain + ONE coarse
// "fire at-or-before here" test; exact per-element tests only on replay of
// the firing group. One Lambert solve at the end.
// Coarse test (exact-math equivalent of "exists valid k <= K"):
//   reach_K:  A(lnA-1) >= B
//   crossed:  t_{K+1} >= lnA  ||  A*t_{K+1} - B >= z_{K+1}
// ---------------------------------------------------------------------------
__global__ void __launch_bounds__(64)
solve_kernel(float* __restrict__ out) {
    __shared__ float4 spk[STRIDE];

    const int tid = threadIdx.x;
    const int gt  = blockIdx.x * 64 + tid;
    const int b   = gt >> 9;
    const int o   = gt & 511;

    {   // stage this batch row's packed data (coalesced)
        const float4* __restrict__ pk = g_pack + b * STRIDE;
        #pragma unroll
        for (int i = tid; i < STRIDE; i += 64) spk[i] = pk[i];
    }
    __syncthreads();

    const float* __restrict__ wt = g_wt;

    float A = 0.0f, Bv = 0.0f;
    float fA = 1.0f, fB = 0.0f;
    bool  found = false;

    // prime: weights for group 0 (coalesced lines: consecutive o per warp)
    float w[GROUP];
    #pragma unroll
    for (int j = 0; j < GROUP; ++j)
        w[j] = wt[__float_as_int(spk[j].w) * NOUT + o];

    for (int k0 = 0; k0 < NIN; k0 += GROUP) {
        // prefetch next group's weights (idx via fast LDS; pads read row 0)
        float wn[GROUP];
        #pragma unroll
        for (int j = 0; j < GROUP; ++j)
            wn[j] = wt[__float_as_int(spk[k0 + GROUP + j].w) * NOUT + o];

        // accumulate-only pass (pads have z=zt=0 -> no-ops)
        const float A0 = A, B0 = Bv;
        #pragma unroll
        for (int j = 0; j < GROUP; ++j) {
            const float4 p = spk[k0 + j];
            A  = fmaf(w[j], p.y, A);
            Bv = fmaf(w[j], p.z, Bv);
        }

        // coarse group test
        const float4 q = spk[k0 + GROUP];
        bool coarse = false;
        if (!found && A > 1e-10f) {
            const float lnA = __logf(A);
            coarse = (fmaf(A, lnA - 1.0f, -Bv) >= 0.0f)
                  && ((q.x >= lnA) || (fmaf(A, q.x, -Bv) >= q.y));
        }

        if (coarse) {
            // replay this group with exact per-element tests
            float Ar = A0, Br = B0;
            #pragma unroll
            for (int j = 0; j < GROUP; ++j) {
                const float4 p = spk[k0 + j];
                Ar = fmaf(w[j], p.y, Ar);
                Br = fmaf(w[j], p.z, Br);
                const float tn = (j < GROUP - 1) ? spk[k0 + j + 1].x : q.x;
                const float zn = (j < GROUP - 1) ? spk[k0 + j + 1].y : q.y;
                const float lnA = __logf(Ar);
                const bool valid =
                       (Ar > 1e-10f)
                    && (fmaf(Ar, lnA - 1.0f, -Br) >= 0.0f)
                    && (fmaf(Ar, p.x, -Br) <= p.y)
                    && ((tn >= lnA) || (fmaf(Ar, tn, -Br) >= zn))
                    && (p.x < KNS);
                const bool take = valid && !found;
                fA = take ? Ar : fA;
                fB = take ? Br : fB;
                found |= valid;
            }
        }

        if (__all_sync(0xffffffffu, found)) break;

        #pragma unroll
        for (int j = 0; j < GROUP; ++j) w[j] = wn[j];
    }

    // one Lambert solve per thread
    float tc = KNS;
    if (found) {
        const float boa = fB / fA;
        float xw = -1.0f / fA * expf(fminf(boa, 80.0f));
        xw = fmaxf(fminf(xw, 0.0f), MINW);
        float wv;
        if (xw < -0.25f) {
            const float pbr = sqrtf(fmaxf(2.0f * (1.0f + EF * xw), 0.0f));
            wv = -1.0f + pbr * (1.0f + pbr * (-0.33333333f + pbr * 0.15277778f));
        } else {
            wv = xw * (1.0f - xw * (1.0f - 1.5f * xw));
        }
        #pragma unroll
        for (int it = 0; it < 3; ++it) {
            const float ew = expf(wv);
            const float f  = wv * ew - xw;
            const float denom = ew * (wv + 1.0f)
                      - (wv + 2.0f) * f / (2.0f * (wv + 1.0f) + 1e-12f);
            wv = wv - f / (denom + 1e-12f);
        }
        tc = boa - wv;
    }
    out[b * NOUT + o] = tc;
}

// ---------------------------------------------------------------------------
extern "C" void kernel_launch(void* const* d_in, const int* in_sizes, int n_in,
                              void* d_out, int out_size) {
    const float* x      = (const float*)d_in[0];   // [32, 1024]
    const float* weight = (const float*)d_in[1];   // [512, 1034]
    const float* pulse  = (const float*)d_in[2];   // [10]
    float* out = (float*)d_out;                    // [32, 512]

    prep_kernel<<<NB + ITILES * OTILES, 1024>>>(x, pulse, weight);

    // one thread per (b,o); 64-thr blocks -> 256 blocks (spread across SMs)
    solve_kernel<<<(NB * NOUT) / 64, 64>>>(out);
}